// round 17
// baseline (speedup 1.0000x reference)
#include <cuda_runtime.h>
#include <math.h>

#define NB 2049
#define S_ 2048
#define W_ 64
#define D_ 300
#define M_ 100
#define H_ 8
#define D2_ 200
#define V_ 50000
#define RSQ 0.07071067811865475f   // 1/sqrt(200)

#define RPB 28                     // rows per LSTM block
#define RH 14                      // rows per thread-half

typedef unsigned long long u64;

// ----------------------------- device scratch ------------------------------
__device__ float g_EW[V_ * 800];          // emb @ [w_ih_f | w_ih_b]^T
__device__ float g_embR[V_ * 300];        // tf32-rounded emb
__device__ float g_wihR[800 * 300];       // tf32-rounded [wihf; wihb]
__device__ float g_qwR[H_ * D2_ * D2_];
__device__ float g_kwR[H_ * D2_ * D2_];
__device__ float g_vwR[H_ * D2_ * D2_];
__device__ float g_cwR[D2_ * 1600];
__device__ float g_hid[NB * D2_];         // [h_f | h_b]
__device__ float g_hv[D2_];
__device__ float g_logit[S_];
__device__ float g_prob[S_];
__device__ float g_att[S_ * D2_];
__device__ float g_Qa[H_ * S_ * D2_];
__device__ float g_Ka[H_ * S_ * D2_];
__device__ float g_Va[H_ * S_ * D2_];
__device__ float g_Qc[H_ * S_ * D2_];
__device__ float g_Kc[H_ * S_ * D2_];
__device__ float g_Vc[H_ * S_ * D2_];
__device__ float g_SC[33554432];          // 8 * 2048 * 2048: E = exp(scores)
__device__ float g_iZ[H_ * S_];
__device__ float g_cat[S_ * H_ * D2_];    // out in cat layout [s][h*200+o]
__device__ float g_mh[S_ * D2_];
__device__ float g_fp[2 * 8 * D2_];
__device__ int   g_idx[2][S_];
__device__ int   g_n[2];

__device__ __forceinline__ unsigned f2tf(float v) {
    unsigned r; asm("cvt.rna.tf32.f32 %0, %1;" : "=r"(r) : "f"(v)); return r;
}
__device__ __forceinline__ float tfr(float v) {
    return __uint_as_float(f2tf(v));
}
// exp(x) for |x| < 0.3 : degree-4 Taylor (FMA pipe, avoids MUFU)
__device__ __forceinline__ float pexp(float x) {
    return 1.f + x * (1.f + x * (0.5f + x * (0.16666667f + x * 0.041666668f)));
}
__device__ __forceinline__ u64 ffma2(u64 a, u64 b, u64 c) {
    u64 d; asm("fma.rn.f32x2 %0, %1, %2, %3;" : "=l"(d) : "l"(a), "l"(b), "l"(c)); return d;
}
__device__ __forceinline__ void upk2(u64 v, float& lo, float& hi) {
    asm("mov.b64 {%0,%1}, %2;" : "=f"(lo), "=f"(hi) : "l"(v));
}

__device__ __forceinline__ unsigned sptr(const void* p) {
    return (unsigned)__cvta_generic_to_shared(p);
}
__device__ __forceinline__ void cpa16(unsigned dst, const void* src, int bytes) {
    asm volatile("cp.async.cg.shared.global [%0], [%1], 16, %2;\n"
                 :: "r"(dst), "l"(src), "r"(bytes));
}
__device__ __forceinline__ void cpa_commit() {
    asm volatile("cp.async.commit_group;\n" ::: "memory");
}
__device__ __forceinline__ void cpa_wait0() {
    asm volatile("cp.async.wait_group 0;\n" ::: "memory");
}

// --------- TF32 tensor GEMM, cp.async double-buffered, BK=32 ---------------
// All operands must be pre-rounded to tf32 (RNA) by producers.
#define BM 128
#define BN 64
#define BK 32
#define A_STR 36          // [m][k] row stride
#define BT_STR 36         // transB: [n][k] row stride
#define BN_STR 72         // noT:    [k][n] row stride
#define A_BUF 4608        // 128*36
#define B_BUF 2304        // 64*36 == 32*72
#define B_BASE 9216       // 2*A_BUF

__global__ void __launch_bounds__(256)
tgemm(const float* __restrict__ A, int lda, long long sA,
      const float* __restrict__ B, int ldb, long long sB, int transB,
      float* __restrict__ C, int ldc, long long sC,
      int M, int N, int K,
      const float* __restrict__ bias, int sBias,
      int limBr, int limRows, int limCols, int capK, int epi,
      int aClampK, int roundC)
{
    extern __shared__ float dsh[];
    int bz = blockIdx.z;
    int m0 = blockIdx.y * BM;
    int n0 = blockIdx.x * BN;
    int lim = 0x7fffffff;
    if (limBr >= 0) {
        lim = g_n[limBr];
        if (limRows && m0 >= lim) return;
        if (limCols && n0 >= lim) return;
        if (capK) { int kc = (lim + 15) & ~15; if (kc < K) K = kc; }
    }
    int limK = aClampK ? (lim < K ? lim : K) : K;
    A += (long long)bz * sA;
    B += (long long)bz * sB;
    C += (long long)bz * sC;

    int tid = threadIdx.x;            // 256 threads = 8 warps (4m x 2n)
    int lane = tid & 31;
    int wrp = tid >> 5;
    int wm = (wrp & 3) * 32;
    int wn = (wrp >> 2) * 32;
    int grp = lane >> 2;
    int four = lane & 3;

    float acc[2][4][4];
#pragma unroll
    for (int i = 0; i < 2; i++)
#pragma unroll
        for (int j = 0; j < 4; j++)
#pragma unroll
            for (int q = 0; q < 4; q++) acc[i][j][q] = 0.f;

    unsigned shb = sptr(dsh);
    unsigned asb[2] = { shb, shb + A_BUF * 4 };
    unsigned bsb[2] = { shb + B_BASE * 4, shb + (B_BASE + B_BUF) * 4 };

    auto stage = [&](int k0v, int b) {
#pragma unroll
        for (int i = 0; i < 4; i++) {
            int e = tid + i * 256;
            int m = e >> 3, kc = (e & 7) * 4;
            int gm = m0 + m, gk = k0v + kc;
            int rem = limK - gk; if (rem > 4) rem = 4; if (rem < 0) rem = 0;
            int bytes = (gm < M) ? rem * 4 : 0;
            cpa16(asb[b] + (m * A_STR + kc) * 4,
                  A + (long long)(gm < M ? gm : 0) * lda + (gk < K ? gk : 0), bytes);
        }
        if (transB) {
#pragma unroll
            for (int i = 0; i < 2; i++) {
                int e = tid + i * 256;
                int n = e >> 3, kc = (e & 7) * 4;
                int gn = n0 + n, gk = k0v + kc;
                int rem = K - gk; if (rem > 4) rem = 4; if (rem < 0) rem = 0;
                int bytes = (gn < N) ? rem * 4 : 0;
                cpa16(bsb[b] + (n * BT_STR + kc) * 4,
                      B + (long long)(gn < N ? gn : 0) * ldb + (gk < K ? gk : 0), bytes);
            }
        } else {
#pragma unroll
            for (int i = 0; i < 2; i++) {
                int e = tid + i * 256;
                int k = e >> 4, nc = (e & 15) * 4;
                int gk = k0v + k, gn = n0 + nc;
                int rem = N - gn; if (rem > 4) rem = 4; if (rem < 0) rem = 0;
                int bytes = (gk < K) ? rem * 4 : 0;
                cpa16(bsb[b] + (k * BN_STR + nc) * 4,
                      B + (long long)(gk < K ? gk : 0) * ldb + (rem ? gn : 0), bytes);
            }
        }
    };

    stage(0, 0);
    cpa_commit();

    int buf = 0;
    for (int k0v = 0; k0v < K; k0v += BK) {
        cpa_wait0();
        __syncthreads();
        int kn = k0v + BK;
        if (kn < K) { stage(kn, buf ^ 1); cpa_commit(); }

        const float* Ab = dsh + buf * A_BUF;
        const float* Bb = dsh + B_BASE + buf * B_BUF;
#pragma unroll
        for (int kk = 0; kk < BK; kk += 8) {
            unsigned a[2][4];
#pragma unroll
            for (int ma = 0; ma < 2; ma++) {
                int mb = wm + ma * 16 + grp;
                a[ma][0] = __float_as_uint(Ab[mb * A_STR + kk + four]);
                a[ma][1] = __float_as_uint(Ab[(mb + 8) * A_STR + kk + four]);
                a[ma][2] = __float_as_uint(Ab[mb * A_STR + kk + 4 + four]);
                a[ma][3] = __float_as_uint(Ab[(mb + 8) * A_STR + kk + 4 + four]);
            }
#pragma unroll
            for (int na = 0; na < 4; na++) {
                int nb = wn + na * 8 + grp;
                unsigned b0, b1;
                if (transB) {
                    b0 = __float_as_uint(Bb[nb * BT_STR + kk + four]);
                    b1 = __float_as_uint(Bb[nb * BT_STR + kk + 4 + four]);
                } else {
                    b0 = __float_as_uint(Bb[(kk + four) * BN_STR + nb]);
                    b1 = __float_as_uint(Bb[(kk + 4 + four) * BN_STR + nb]);
                }
#pragma unroll
                for (int ma = 0; ma < 2; ma++) {
                    asm("mma.sync.aligned.m16n8k8.row.col.f32.tf32.tf32.f32 "
                        "{%0,%1,%2,%3}, {%4,%5,%6,%7}, {%8,%9}, {%0,%1,%2,%3};"
                        : "+f"(acc[ma][na][0]), "+f"(acc[ma][na][1]),
                          "+f"(acc[ma][na][2]), "+f"(acc[ma][na][3])
                        : "r"(a[ma][0]), "r"(a[ma][1]), "r"(a[ma][2]), "r"(a[ma][3]),
                          "r"(b0), "r"(b1));
                }
            }
        }
        buf ^= 1;
    }

#pragma unroll
    for (int ma = 0; ma < 2; ma++) {
#pragma unroll
        for (int na = 0; na < 4; na++) {
            int gmb = m0 + wm + ma * 16 + grp;
            int gnb = n0 + wn + na * 8 + 2 * four;
#pragma unroll
            for (int q = 0; q < 4; q++) {
                int gm = gmb + (q >> 1) * 8;
                int gn = gnb + (q & 1);
                if (gm >= M || gn >= N) continue;
                float v = acc[ma][na][q];
                if (bias) v += bias[bz * sBias + gn];
                if (epi == 1) v *= RSQ;
                else if (epi == 2) v = (1.f - v) * RSQ;
                else if (epi == 3) v = pexp(v * RSQ);
                else if (epi == 4) v = pexp((1.f - v) * RSQ);
                if (roundC) v = tfr(v);
                C[(long long)gm * ldc + gn] = v;
            }
        }
    }
}

#define TG_SMEM ((2 * A_BUF + 2 * B_BUF) * 4)

// -------------------------- tf32 round-copy pass ----------------------------
__global__ void roundcp(const float* __restrict__ src, float* __restrict__ dst, int n)
{
    int i = blockIdx.x * 256 + threadIdx.x;
    if (i < n) dst[i] = tfr(src[i]);
}

// ------------------------- fused all-timestep LSTM --------------------------
// Gate-paired f32x2 inner loop: (w_i,w_f)/(w_g,w_o) are natural float2 loads
// from the gate-interleaved Wg; h stored duplicated (h,h) in hTd so the
// broadcast LDS.64 directly yields the packed operand. 28 FFMA2 per m
// replaces 56 FFMA (bit-exact fp32 per lane).
__global__ void __launch_bounds__(256, 1)
lstm_all(const int* __restrict__ rsent, const int* __restrict__ body,
         const float* __restrict__ whf, const float* __restrict__ whb,
         const float* __restrict__ bihf, const float* __restrict__ bhhf,
         const float* __restrict__ bihb, const float* __restrict__ bhhb)
{
    extern __shared__ float sh[];
    float* Wg  = sh;                    // [100][100][4] gate-interleaved (40000)
    float* hTd = sh + 40000;            // [100][60]: (h,h) pairs per row (6000)
    float* bcs = sh + 46000;            // [400]
    int*   toks = (int*)(sh + 46400);   // [28]

    int dir = blockIdx.y;
    int n0 = blockIdx.x * RPB;
    int tid = threadIdx.x;

    const float* wh = dir ? whb : whf;
    const float* bi = dir ? bihb : bihf;
    const float* bh = dir ? bhhb : bhhf;

    // Wg[m*400 + m2*4 + gate] = wh[(gate*100 + m2)*100 + m]
    for (int e = tid; e < 40000; e += 256) {
        int j = e / 100, m = e - j * 100;
        int gate = j / 100, m2s = j - gate * 100;
        Wg[m * 400 + m2s * 4 + gate] = wh[e];
    }
    for (int j = tid; j < 400; j += 256) bcs[j] = bi[j] + bh[j];
    for (int e = tid; e < 6000; e += 256) hTd[e] = 0.f;

    int m2 = tid & 127;
    int half = tid >> 7;
    int rbase = half * RH;
    bool act = (m2 < 100);

    if (tid < RPB) {
        int w0 = dir ? 63 : 0;
        int n = n0 + tid;
        if (n >= NB) n = NB - 1;
        toks[tid] = (n == 0) ? rsent[w0] : body[(n - 1) * W_ + w0];
    }
    __syncthreads();

    float bj[4];
    if (act) {
#pragma unroll
        for (int jo = 0; jo < 4; jo++) bj[jo] = bcs[m2 + jo * 100];
    }

    float c[RH];
#pragma unroll
    for (int r = 0; r < RH; r++) c[r] = 0.f;

    for (int t = 0; t < 64; t++) {
        float ew[4][RH];
        u64 accIF[RH], accGO[RH];
        if (act) {
            // scattered gathers issue first; scoreboard-overlap the m-loop
#pragma unroll
            for (int jo = 0; jo < 4; jo++) {
                int j = m2 + jo * 100;
#pragma unroll
                for (int r = 0; r < RH; r++)
                    ew[jo][r] = g_EW[(long long)toks[rbase + r] * 800 + dir * 400 + j];
            }
#pragma unroll
            for (int r = 0; r < RH; r++) { accIF[r] = 0ull; accGO[r] = 0ull; }

            const float* wrow = &Wg[m2 * 4];
            for (int m = 0; m < 100; m++) {
                u64 w01 = *reinterpret_cast<const u64*>(&wrow[m * 400]);
                u64 w23 = *reinterpret_cast<const u64*>(&wrow[m * 400 + 2]);
                const u64* hp = reinterpret_cast<const u64*>(&hTd[m * 60 + 2 * rbase]);
#pragma unroll
                for (int r = 0; r < RH; r++) {
                    u64 hd = hp[r];
                    accIF[r] = ffma2(w01, hd, accIF[r]);
                    accGO[r] = ffma2(w23, hd, accGO[r]);
                }
            }
        }
        __syncthreads();   // hTd + toks reads done before overwrite
        if (act) {
#pragma unroll
            for (int r = 0; r < RH; r++) {
                float gi, gf, gg, go;
                upk2(accIF[r], gi, gf);
                upk2(accGO[r], gg, go);
                gi += ew[0][r] + bj[0];
                gf += ew[1][r] + bj[1];
                gg += ew[2][r] + bj[2];
                go += ew[3][r] + bj[3];
                float fi = 1.f / (1.f + expf(-gi));
                float ff = 1.f / (1.f + expf(-gf));
                float fo = 1.f / (1.f + expf(-go));
                c[r] = ff * c[r] + fi * tanhf(gg);
                float h = fo * tanhf(c[r]);
                *reinterpret_cast<float2*>(&hTd[m2 * 60 + 2 * (rbase + r)]) =
                    make_float2(h, h);
            }
        }
        int tn = t + 1;
        if (tn < 64 && tid < RPB) {
            int w = dir ? (63 - tn) : tn;
            int n = n0 + tid;
            if (n >= NB) n = NB - 1;
            toks[tid] = (n == 0) ? rsent[w] : body[(n - 1) * W_ + w];
        }
        __syncthreads();   // new hTd + toks visible
    }

    if (act) {
#pragma unroll
        for (int r = 0; r < RH; r++) {
            int n = n0 + rbase + r;
            if (n < NB) g_hid[n * D2_ + dir * M_ + m2] = hTd[m2 * 60 + 2 * (rbase + r)];
        }
    }
}

// ----------------------------- sim / partition -----------------------------
__global__ void hv_k(const float* __restrict__ simw)
{
    int warp = threadIdx.x >> 5, lane = threadIdx.x & 31;
    int b = blockIdx.x * 32 + warp;
    if (b >= D2_) return;
    float a = 0.f;
    for (int i = lane; i < D2_; i += 32) a += g_hid[i] * simw[i * D2_ + b];
#pragma unroll
    for (int o = 16; o; o >>= 1) a += __shfl_down_sync(0xffffffffu, a, o);
    if (lane == 0) g_hv[b] = a;
}

__global__ void logits_k(const float* __restrict__ simb)
{
    __shared__ float hv[D2_];
    int tid = threadIdx.x;
    if (tid < D2_) hv[tid] = g_hv[tid];
    __syncthreads();
    int warp = tid >> 5, lane = tid & 31;
    int s = blockIdx.x * 8 + warp;
    const float* row = g_hid + (long long)(s + 1) * D2_;
    float a = 0.f;
    for (int b = lane; b < D2_; b += 32) a += hv[b] * row[b];
#pragma unroll
    for (int o = 16; o; o >>= 1) a += __shfl_down_sync(0xffffffffu, a, o);
    if (lane == 0) g_logit[s] = a + simb[0];
}

__global__ void softpart()
{
    __shared__ float sg[S_];
    __shared__ float redm[32];
    __shared__ float reds[32];
    __shared__ int cnt[1024];
    int tid = threadIdx.x;           // 1024
    for (int s = tid; s < S_; s += 1024) {
        float l = g_logit[s];
        sg[s] = 1.f / (1.f + expf(-l));
    }
    __syncthreads();
    float m = fmaxf(sg[tid], sg[tid + 1024]);
#pragma unroll
    for (int o = 16; o; o >>= 1) m = fmaxf(m, __shfl_xor_sync(0xffffffffu, m, o));
    if ((tid & 31) == 0) redm[tid >> 5] = m;
    __syncthreads();
    if (tid < 32) {
        float v = redm[tid];
#pragma unroll
        for (int o = 16; o; o >>= 1) v = fmaxf(v, __shfl_xor_sync(0xffffffffu, v, o));
        if (tid == 0) redm[0] = v;
    }
    __syncthreads();
    float mx = redm[0];
    float z = expf(sg[tid] - mx) + expf(sg[tid + 1024] - mx);
#pragma unroll
    for (int o = 16; o; o >>= 1) z += __shfl_xor_sync(0xffffffffu, z, o);
    if ((tid & 31) == 0) reds[tid >> 5] = z;
    __syncthreads();
    if (tid < 32) {
        float v = reds[tid];
#pragma unroll
        for (int o = 16; o; o >>= 1) v += __shfl_xor_sync(0xffffffffu, v, o);
        if (tid == 0) reds[0] = v;
    }
    __syncthreads();
    float invZ = 1.f / reds[0];
    for (int s = tid; s < S_; s += 1024) g_prob[s] = expf(sg[s] - mx) * invZ;

    int a = (sg[2 * tid] >= 0.5f) ? 1 : 0;
    int b = (sg[2 * tid + 1] >= 0.5f) ? 1 : 0;
    cnt[tid] = a + b;
    __syncthreads();
    for (int off = 1; off < 1024; off <<= 1) {
        int v = cnt[tid];
        int u = (tid >= off) ? cnt[tid - off] : 0;
        __syncthreads();
        cnt[tid] = v + u;
        __syncthreads();
    }
    int pre = (tid > 0) ? cnt[tid - 1] : 0;
    int tot = cnt[1023];
    int s0 = 2 * tid, s1 = 2 * tid + 1;
    if (a) g_idx[0][pre] = s0; else g_idx[1][s0 - pre] = s0;
    int pre1 = pre + a;
    if (b) g_idx[0][pre1] = s1; else g_idx[1][s1 - pre1] = s1;
    if (tid == 0) { g_n[0] = tot; g_n[1] = S_ - tot; }
}

__global__ void attend_k()
{
    int e = blockIdx.x * 256 + threadIdx.x;
    if (e >= S_ * D2_) return;
    int s = e / D2_;
    g_att[e] = tfr(g_prob[s] * g_hid[e + D2_]);
}

// -------------------------- branch-local kernels ---------------------------
__global__ void compact(int br)
{
    int p = blockIdx.x;
    if (p >= g_n[br]) return;
    int src = g_idx[br][p];
    for (int e = threadIdx.x; e < H_ * D2_; e += 192) {
        int h = e / D2_, o = e - h * D2_;
        long long di = (long long)h * (S_ * D2_) + (long long)p * D2_ + o;
        long long si = (long long)h * (S_ * D2_) + (long long)src * D2_ + o;
        g_Qc[di] = g_Qa[si];
        g_Kc[di] = g_Ka[si];
        g_Vc[di] = g_Va[si];
    }
}

// column sums of E (no max-subtraction needed: |scores·RSQ| << 1)
__global__ void colsum(int br)
{
    int n = g_n[br];
    int t = blockIdx.x * 128 + threadIdx.x;
    if (t >= n) return;
    int h = blockIdx.y;
    const float* base = g_SC + (long long)h * S_ * S_ + t;
    float z = 0.f;
    int s = 0;
    for (; s + 4 <= n; s += 4) {
        float v0 = base[(long long)s * S_];
        float v1 = base[(long long)(s + 1) * S_];
        float v2 = base[(long long)(s + 2) * S_];
        float v3 = base[(long long)(s + 3) * S_];
        z += (v0 + v1) + (v2 + v3);
    }
    for (; s < n; s++) z += base[(long long)s * S_];
    g_iZ[h * S_ + t] = 1.f / z;
}

// Vc[h][t][o] *= iZ[h][t], rounded to tf32 (feeds out-gemm)
__global__ void scaleV(int br)
{
    int id = blockIdx.x * 256 + threadIdx.x;
    if (id >= H_ * S_ * D2_) return;
    int h = id / (S_ * D2_);
    int r = id - h * (S_ * D2_);
    int t = r / D2_;
    if (t < g_n[br]) g_Vc[id] = tfr(g_Vc[id] * g_iZ[h * S_ + t]);
}

__global__ void featpart(const float* __restrict__ fw, int br)
{
    int n = g_n[br];
    int j = blockIdx.x;
    int ch = blockIdx.y;
    int per = (n + 7) / 8;
    int s0 = ch * per;
    int s1 = s0 + per; if (s1 > n) s1 = n;
    if (s0 > n) s0 = n;
    float acc = 0.f;
    const float* base = fw + (long long)j * (S_ * D2_);
    for (long long e = (long long)s0 * D2_ + threadIdx.x; e < (long long)s1 * D2_; e += 256)
        acc += g_mh[e] * base[e];
    __shared__ float red[8];
#pragma unroll
    for (int o = 16; o; o >>= 1) acc += __shfl_xor_sync(0xffffffffu, acc, o);
    if ((threadIdx.x & 31) == 0) red[threadIdx.x >> 5] = acc;
    __syncthreads();
    if (threadIdx.x < 8) {
        float v = red[threadIdx.x];
#pragma unroll
        for (int o = 4; o; o >>= 1) v += __shfl_xor_sync(0x000000ffu, v, o);
        if (threadIdx.x == 0) g_fp[(br * 8 + ch) * D2_ + j] = v;
    }
}

__global__ void finalize(const float* __restrict__ fb, float* __restrict__ out)
{
    int i = blockIdx.x * 256 + threadIdx.x;
    if (i >= 400) return;
    int br = i / 200, j = i - br * 200;
    float a = fb[j];
    for (int c = 0; c < 8; c++) a += g_fp[(br * 8 + c) * D2_ + j];
    out[i] = a;
}

// --------------------------------- launcher --------------------------------
extern "C" void kernel_launch(void* const* d_in, const int* in_sizes, int n_in,
                              void* d_out, int out_size)
{
    const int*   rsent = (const int*)d_in[0];
    const int*   body  = (const int*)d_in[1];
    const float* emb   = (const float*)d_in[2];
    const float* wihf  = (const float*)d_in[3];
    const float* whhf  = (const float*)d_in[4];
    const float* bihf  = (const float*)d_in[5];
    const float* bhhf  = (const float*)d_in[6];
    const float* wihb  = (const float*)d_in[7];
    const float* whhb  = (const float*)d_in[8];
    const float* bihb  = (const float*)d_in[9];
    const float* bhhb  = (const float*)d_in[10];
    const float* simw  = (const float*)d_in[11];
    const float* simb  = (const float*)d_in[12];
    const float* qw    = (const float*)d_in[13];
    const float* qb    = (const float*)d_in[14];
    const float* kw    = (const float*)d_in[15];
    const float* kb    = (const float*)d_in[16];
    const float* vw    = (const float*)d_in[17];
    const float* vb    = (const float*)d_in[18];
    const float* cw    = (const float*)d_in[19];
    const float* cb    = (const float*)d_in[20];
    const float* fw    = (const float*)d_in[21];
    const float* fb    = (const float*)d_in[22];
    float* out = (float*)d_out;

    float *pEW, *pEmbR, *pWihR, *pQwR, *pKwR, *pVwR, *pCwR;
    float *pAtt, *pQa, *pKa, *pVa, *pQc, *pKc, *pVc, *pSC, *pCat, *pMh;
    cudaGetSymbolAddress((void**)&pEW, g_EW);
    cudaGetSymbolAddress((void**)&pEmbR, g_embR);
    cudaGetSymbolAddress((void**)&pWihR, g_wihR);
    cudaGetSymbolAddress((void**)&pQwR, g_qwR);
    cudaGetSymbolAddress((void**)&pKwR, g_kwR);
    cudaGetSymbolAddress((void**)&pVwR, g_vwR);
    cudaGetSymbolAddress((void**)&pCwR, g_cwR);
    cudaGetSymbolAddress((void**)&pAtt, g_att);
    cudaGetSymbolAddress((void**)&pQa, g_Qa);
    cudaGetSymbolAddress((void**)&pKa, g_Ka);
    cudaGetSymbolAddress((void**)&pVa, g_Va);
    cudaGetSymbolAddress((void**)&pQc, g_Qc);
    cudaGetSymbolAddress((void**)&pKc, g_Kc);
    cudaGetSymbolAddress((void**)&pVc, g_Vc);
    cudaGetSymbolAddress((void**)&pSC, g_SC);
    cudaGetSymbolAddress((void**)&pCat, g_cat);
    cudaGetSymbolAddress((void**)&pMh, g_mh);

    cudaFuncSetAttribute(tgemm, cudaFuncAttributeMaxDynamicSharedMemorySize, TG_SMEM);

    // ---- tf32 pre-round of external GEMM operands ----
    roundcp<<<58594, 256>>>(emb, pEmbR, V_ * 300);
    roundcp<<<469, 256>>>(wihf, pWihR, 120000);
    roundcp<<<469, 256>>>(wihb, pWihR + 120000, 120000);
    roundcp<<<1250, 256>>>(qw, pQwR, 320000);
    roundcp<<<1250, 256>>>(kw, pKwR, 320000);
    roundcp<<<1250, 256>>>(vw, pVwR, 320000);
    roundcp<<<1250, 256>>>(cw, pCwR, 320000);

    // EW = embR @ wihR^T  (fused both directions, N=800)
    dim3 ge(13, 391, 1);
    tgemm<<<ge, 256, TG_SMEM>>>(pEmbR, 300, 0, pWihR, 300, 0, 1, pEW, 800, 0,
                                V_, 800, 300, nullptr, 0, -1, 0, 0, 0, 0, 0, 0);

    const int SMEM_LSTM = (40000 + 6000 + 400) * 4 + RPB * 4;
    cudaFuncSetAttribute(lstm_all, cudaFuncAttributeMaxDynamicSharedMemorySize, SMEM_LSTM);
    lstm_all<<<dim3(74, 2), 256, SMEM_LSTM>>>(rsent, body, whhf, whhb,
                                              bihf, bhhf, bihb, bhhb);

    hv_k<<<7, 1024>>>(simw);
    logits_k<<<256, 256>>>(simb);
    softpart<<<1, 1024>>>();
    attend_k<<<1600, 256>>>();

    // Q/K/V on full attend, h-batched (z=8); Q,K rounded for scores gemm
    dim3 gq(4, 16, 8);
    tgemm<<<gq, 256, TG_SMEM>>>(pAtt, 200, 0, pQwR, 200, 40000LL, 1, pQa, 200, 409600LL,
                                S_, 200, 200, qb, 200, -1, 0, 0, 0, 0, 0, 1);
    tgemm<<<gq, 256, TG_SMEM>>>(pAtt, 200, 0, pKwR, 200, 40000LL, 1, pKa, 200, 409600LL,
                                S_, 200, 200, kb, 200, -1, 0, 0, 0, 0, 0, 1);
    tgemm<<<gq, 256, TG_SMEM>>>(pAtt, 200, 0, pVwR, 200, 40000LL, 1, pVa, 200, 409600LL,
                                S_, 200, 200, vb, 200, -1, 0, 0, 0, 0, 0, 0);

    for (int br = 0; br < 2; br++) {
        compact<<<2048, 192>>>(br);

        // E[h,s,t] = exp(epi(Qc.Kc)), rounded (feeds out-gemm)
        dim3 gs(32, 16, 8);
        tgemm<<<gs, 256, TG_SMEM>>>(pQc, 200, 409600LL, pKc, 200, 409600LL, 1,
                                    pSC, 2048, 4194304LL, S_, S_, 200,
                                    nullptr, 0, br, 1, 1, 0, (br == 0) ? 4 : 3, 0, 1);

        colsum<<<dim3(16, 8), 128>>>(br);
        scaleV<<<12800, 256>>>(br);

        // out = E @ (iZ*V): A zfilled past n via staging clamp; cat rounded
        dim3 go(4, 16, 8);
        tgemm<<<go, 256, TG_SMEM>>>(pSC, 2048, 4194304LL, pVc, 200, 409600LL, 0,
                                    pCat, 1600, 200LL, S_, 200, S_,
                                    nullptr, 0, br, 1, 0, 1, 0, 1, 1);

        dim3 gm(4, 16, 1);
        tgemm<<<gm, 256, TG_SMEM>>>(pCat, 1600, 0, pCwR, 1600, 0, 1, pMh, 200, 0,
                                    S_, 200, 1600, cb, 0, br, 1, 0, 0, 0, 0, 0);

        featpart<<<dim3(200, 8), 256>>>(fw, br);
    }

    finalize<<<2, 256>>>(fb, out);
}